// round 12
// baseline (speedup 1.0000x reference)
#include <cuda_runtime.h>
#include <cuda_fp16.h>
#include <cstdint>
#include <math.h>

// Problem constants
#define B_   4
#define T_   8192
#define H_   1024
#define D_   1024
#define M_   (B_*T_)     // 32768
#define CH   128
#define NC   (T_/CH)     // 64
#define NPRE 2048
#define BCK  16

// ---------------- scratch (device globals) ------------------------------------
__device__ __half g_xh[(size_t)M_*D_];       // fp16 x
__device__ __half g_preh[(size_t)M_*NPRE];   // interleaved (P, h_local) __half2 per channel
__device__ __half g_hn[(size_t)M_*H_];       // layernormed h (fp16)
__device__ __half g_WcatT[(size_t)NPRE*D_];  // interleaved: row 2h=W_ih^T_h, 2h+1=W_gate^T_h
__device__ __half g_WoutH[(size_t)H_*H_];    // W_out fp16 row-major
__device__ __half g_WprojT[(size_t)D_*H_];   // W_proj^T fp16 [D][H]
__device__ __half g_WcT[(size_t)D_*H_];      // (W_out@W_proj)^T fp16 [D][H]
__device__ float  g_bcp[BCK*D_];
__device__ float  g_bc[D_];                  // b_out@W_proj + b_proj
__device__ float  g_cA[B_*NC*H_];
__device__ float  g_cB[B_*NC*H_];
__device__ float  g_cP[B_*NC*H_];

// ---------------- helpers -------------------------------------------------------
__device__ __forceinline__ void cp16(void* smem_dst, const void* gptr) {
    uint32_t s = (uint32_t)__cvta_generic_to_shared(smem_dst);
    asm volatile("cp.async.cg.shared.global [%0], [%1], 16;\n" :: "r"(s), "l"(gptr));
}
__device__ __forceinline__ void mma_f16(float* d, const uint32_t* a, uint32_t b0, uint32_t b1) {
    asm volatile(
        "mma.sync.aligned.m16n8k16.row.col.f32.f16.f16.f32 "
        "{%0,%1,%2,%3}, {%4,%5,%6,%7}, {%8,%9}, {%0,%1,%2,%3};\n"
        : "+f"(d[0]), "+f"(d[1]), "+f"(d[2]), "+f"(d[3])
        : "r"(a[0]), "r"(a[1]), "r"(a[2]), "r"(a[3]), "r"(b0), "r"(b1));
}
#define LDSM4(r, addr)                                                            \
    asm volatile("ldmatrix.sync.aligned.m8n8.x4.shared.b16 {%0,%1,%2,%3}, [%4];"  \
        : "=r"((r)[0]), "=r"((r)[1]), "=r"((r)[2]), "=r"((r)[3]) : "r"(addr))

// ---------------- FP16 tensor-core GEMM (R8-best config + row_base) -------------
// C[M,N] = A[M,K](fp16 rm) @ Bt[N,K](fp16 rm)^T + bias[N]; rows offset by row_base.
// mode 0: fp32 store (+bias). mode 1: fused chunk-scan epilogue (fp16 pair store).
// mode 2: fp16 store, no bias.
#define BM 128
#define BN 128
#define BK 64
#define ASTR 72
#define AS_HALFS (BM*ASTR)
#define BS_HALFS (BN*ASTR)
#define STG_HALFS (AS_HALFS+BS_HALFS)
#define STAGES 3
#define SMEM_BYTES (STAGES*STG_HALFS*2)   // 110592
#define SSTR 68

__global__ void __launch_bounds__(256, 2) gemm_f16(
    const __half* __restrict__ A, const __half* __restrict__ Bt,
    const float* __restrict__ bias, const float* __restrict__ bias2,
    float* __restrict__ C,
    int K, int N, int mode, const float* __restrict__ log_a, int row_base)
{
    extern __shared__ __half smh[];

    const int tid  = threadIdx.x;
    const int lane = tid & 31;
    const int warp = tid >> 5;
    const int g    = lane >> 2;
    const int tig  = lane & 3;
    const int wm   = warp & 1;
    const int wn   = warp >> 1;
    const int row0 = row_base + blockIdx.y * BM;   // global row
    const int col0 = blockIdx.x * BN;

    float acc[4][4][4];
    #pragma unroll
    for (int i = 0; i < 4; i++)
        #pragma unroll
        for (int j = 0; j < 4; j++)
            #pragma unroll
            for (int r = 0; r < 4; r++) acc[i][j][r] = 0.f;

    const int NT = K / BK;

    const uint32_t S0 = (uint32_t)__cvta_generic_to_shared(smh);
    const uint32_t aoff = ((wm * 64 + (lane & 15)) * ASTR + (lane >> 4) * 8) * 2;
    const uint32_t boff = (AS_HALFS + (wn * 32 + (lane & 7) + (lane >> 4) * 8) * ASTR
                           + ((lane >> 3) & 1) * 8) * 2;

    auto load_tiles = [&](int st, int kt) {
        __half* As = smh + st * STG_HALFS;
        __half* Bs = As + AS_HALFS;
        const __half* gA = A  + (size_t)row0 * K + kt * BK;
        const __half* gB = Bt + (size_t)col0 * K + kt * BK;
        #pragma unroll
        for (int i = 0; i < 4; i++) {
            int idx = tid + 256 * i;
            int r = idx >> 3, c = idx & 7;
            cp16(As + r * ASTR + c * 8, gA + (size_t)r * K + c * 8);
        }
        #pragma unroll
        for (int i = 0; i < 4; i++) {
            int idx = tid + 256 * i;
            int r = idx >> 3, c = idx & 7;
            cp16(Bs + r * ASTR + c * 8, gB + (size_t)r * K + c * 8);
        }
    };

    load_tiles(0, 0);
    asm volatile("cp.async.commit_group;\n");
    load_tiles(1, 1);
    asm volatile("cp.async.commit_group;\n");
    asm volatile("cp.async.wait_group 1;\n");
    __syncthreads();

    for (int kt = 0; kt < NT; kt++) {
        if (kt + 2 < NT) load_tiles((kt + 2) % STAGES, kt + 2);
        asm volatile("cp.async.commit_group;\n");

        const int st = kt % STAGES;
        const uint32_t aBase = S0 + st * (STG_HALFS * 2) + aoff;
        const uint32_t bBase = S0 + st * (STG_HALFS * 2) + boff;
        #pragma unroll
        for (int ks = 0; ks < 4; ks++) {
            uint32_t af[4][4], bf[2][4];
            #pragma unroll
            for (int mt = 0; mt < 4; mt++)
                LDSM4(af[mt], aBase + (mt * 16 * ASTR + ks * 16) * 2);
            #pragma unroll
            for (int ntp = 0; ntp < 2; ntp++)
                LDSM4(bf[ntp], bBase + (ntp * 16 * ASTR + ks * 16) * 2);
            #pragma unroll
            for (int mt = 0; mt < 4; mt++)
                #pragma unroll
                for (int nt = 0; nt < 4; nt++)
                    mma_f16(acc[mt][nt], af[mt],
                            bf[nt >> 1][(nt & 1) * 2], bf[nt >> 1][(nt & 1) * 2 + 1]);
        }

        asm volatile("cp.async.wait_group 1;\n");
        __syncthreads();
    }

    if (mode == 0) {
        #pragma unroll
        for (int nt = 0; nt < 4; nt++) {
            int c = col0 + wn * 32 + nt * 8 + 2 * tig;
            float b0 = 0.f, b1 = 0.f;
            if (bias) { b0 = bias[c]; b1 = bias[c + 1]; }
            #pragma unroll
            for (int mt = 0; mt < 4; mt++) {
                int r = row0 + wm * 64 + mt * 16 + g;
                float2 v0 = make_float2(acc[mt][nt][0] + b0, acc[mt][nt][1] + b1);
                float2 v1 = make_float2(acc[mt][nt][2] + b0, acc[mt][nt][3] + b1);
                *(float2*)(C + (size_t)r * N + c)       = v0;
                *(float2*)(C + (size_t)(r + 8) * N + c) = v1;
            }
        }
        return;
    }

    if (mode == 2) {   // fp16 store, no bias
        __half2* Ch = (__half2*)C;
        #pragma unroll
        for (int nt = 0; nt < 4; nt++) {
            int c = col0 + wn * 32 + nt * 8 + 2 * tig;
            #pragma unroll
            for (int mt = 0; mt < 4; mt++) {
                int r = row0 + wm * 64 + mt * 16 + g;
                Ch[((size_t)r * N + c) >> 1]       = __floats2half2_rn(acc[mt][nt][0], acc[mt][nt][1]);
                Ch[((size_t)(r + 8) * N + c) >> 1] = __floats2half2_rn(acc[mt][nt][2], acc[mt][nt][3]);
            }
        }
        return;
    }

    // ---- mode 1: fused chunk-local scan epilogue (bias = b_ih, bias2 = b_gate) ----
    float* sA = (float*)smh;            // alpha [128][SSTR]
    float* sB = sA + 128 * SSTR;        // beta

    #pragma unroll
    for (int nt = 0; nt < 4; nt++) {
        const int c    = wn * 32 + nt * 8 + 2 * tig;       // local, even
        const int hloc = c >> 1;
        const int hg   = (col0 >> 1) + hloc;
        const float bi = bias[hg];
        const float bg = bias2[hg];
        const float av = expf(log_a[hg]);
        #pragma unroll
        for (int mt = 0; mt < 4; mt++) {
            const int r = wm * 64 + mt * 16 + g;
            {
                float ih = acc[mt][nt][0] + bi;
                float gp = acc[mt][nt][1] + bg;
                float gt = 1.f / (1.f + __expf(-gp));
                sA[r * SSTR + hloc] = (1.f - gt) * av;
                sB[r * SSTR + hloc] = gt * ih;
            }
            {
                float ih = acc[mt][nt][2] + bi;
                float gp = acc[mt][nt][3] + bg;
                float gt = 1.f / (1.f + __expf(-gp));
                sA[(r + 8) * SSTR + hloc] = (1.f - gt) * av;
                sB[(r + 8) * SSTR + hloc] = gt * ih;
            }
        }
    }
    __syncthreads();

    if (tid < 128) {
        const int h = tid & 63, half = tid >> 6;
        float P = 1.f, hl = 0.f;
        int base = (half * 64) * SSTR + h;
        #pragma unroll 8
        for (int i = 0; i < 64; i++, base += SSTR) {
            float al = sA[base], be = sB[base];
            P *= al;
            hl = fmaf(al, hl, be);
            sA[base] = P;
            sB[base] = hl;
        }
    }
    __syncthreads();

    const int bb  = row0 / T_;
    const int chh = (row0 - bb * T_) >> 7;
    __half2* Ch = (__half2*)C;
    #pragma unroll
    for (int k = 0; k < 32; k++) {
        const int e = tid + 256 * k;
        const int t = e >> 6, h = e & 63;
        float P  = sA[t * SSTR + h];
        float hl = sB[t * SSTR + h];
        if (t >= 64) {
            const float Pm = sA[63 * SSTR + h];
            const float hm = sB[63 * SSTR + h];
            hl = fmaf(P, hm, hl);
            P  = P * Pm;
        }
        const int hg = (col0 >> 1) + h;
        Ch[(size_t)(row0 + t) * (NPRE / 2) + hg] = __floats2half2_rn(P, hl);
        if (t == 127) {
            const int ci = (bb * NC + chh) * H_ + hg;
            g_cA[ci] = P;
            g_cB[ci] = hl;
        }
    }
}

// ---------------- pre-passes -----------------------------------------------------
__global__ void __launch_bounds__(256) conv_h8(const float4* __restrict__ in,
                                               uint4* __restrict__ out)
{
    const size_t i = (size_t)blockIdx.x * 256 + threadIdx.x;
    float4 v0 = in[2 * i], v1 = in[2 * i + 1];
    __half2 h0 = __floats2half2_rn(v0.x, v0.y);
    __half2 h1 = __floats2half2_rn(v0.z, v0.w);
    __half2 h2 = __floats2half2_rn(v1.x, v1.y);
    __half2 h3 = __floats2half2_rn(v1.z, v1.w);
    uint4 o;
    o.x = *(uint32_t*)&h0; o.y = *(uint32_t*)&h1;
    o.z = *(uint32_t*)&h2; o.w = *(uint32_t*)&h3;
    out[i] = o;
}

// out[C][R] = fp16(in[R][C]^T)
__global__ void __launch_bounds__(256) trans_h(const float* __restrict__ in,
                                               __half* __restrict__ out,
                                               int R, int C)
{
    __shared__ float t[32][33];
    int bx = blockIdx.x * 32, by = blockIdx.y * 32;
    #pragma unroll
    for (int j = 0; j < 32; j += 8)
        t[threadIdx.y + j][threadIdx.x] =
            in[(size_t)(by + threadIdx.y + j) * C + bx + threadIdx.x];
    __syncthreads();
    #pragma unroll
    for (int j = 0; j < 32; j += 8)
        out[(size_t)(bx + threadIdx.y + j) * R + by + threadIdx.x] =
            __float2half_rn(t[threadIdx.x][threadIdx.y + j]);
}

// interleaved transpose: out[2*col + sel][row] = fp16(in[row][col]); in [R][C]
__global__ void __launch_bounds__(256) trans_h_il(const float* __restrict__ in,
                                                  __half* __restrict__ out,
                                                  int R, int C, int sel)
{
    __shared__ float t[32][33];
    int bx = blockIdx.x * 32, by = blockIdx.y * 32;
    #pragma unroll
    for (int j = 0; j < 32; j += 8)
        t[threadIdx.y + j][threadIdx.x] =
            in[(size_t)(by + threadIdx.y + j) * C + bx + threadIdx.x];
    __syncthreads();
    #pragma unroll
    for (int j = 0; j < 32; j += 8)
        out[(size_t)(2 * (bx + threadIdx.y + j) + sel) * R + by + threadIdx.x] =
            __float2half_rn(t[threadIdx.x][threadIdx.y + j]);
}

__global__ void __launch_bounds__(256) bias_comb_part(const float* __restrict__ b_out,
                                                      const float* __restrict__ W_proj)
{
    const int d = blockIdx.x * 256 + threadIdx.x;
    const int p = blockIdx.y;
    float acc = 0.f;
    #pragma unroll 8
    for (int hh = p * 64; hh < p * 64 + 64; hh++)
        acc = fmaf(b_out[hh], W_proj[(size_t)hh * D_ + d], acc);
    g_bcp[p * D_ + d] = acc;
}
__global__ void __launch_bounds__(256) bias_comb_final(const float* __restrict__ b_proj)
{
    const int d = blockIdx.x * 256 + threadIdx.x;
    float acc = b_proj[d];
    #pragma unroll
    for (int p = 0; p < BCK; p++) acc += g_bcp[p * D_ + d];
    g_bc[d] = acc;
}

// ---------------- scan pass 2: scan chunk carries (one batch) --------------------
__global__ void __launch_bounds__(256) scan_pass2(int b)
{
    const int h = blockIdx.x * 256 + threadIdx.x;
    float c = 0.f;
    #pragma unroll 4
    for (int ch = 0; ch < NC; ch++) {
        const int i = (b * NC + ch) * H_ + h;
        g_cP[i] = c;
        c = fmaf(g_cA[i], c, g_cB[i]);
    }
}

// ---------------- pass 3: carry fix-up + LayerNorm (fp16 in/out, one batch) ------
__global__ void __launch_bounds__(256) fix_ln(const float* __restrict__ ln_g,
                                              const float* __restrict__ ln_b,
                                              int row_base)
{
    const int row = row_base + blockIdx.x;
    const int b = row / T_, t = row - b * T_;
    const int ch = t / CH;
    const int tx = threadIdx.x;
    const __half2* ph_row = (const __half2*)g_preh + (size_t)row * (NPRE / 2);

    float hv[4];
    float s = 0.f, s2 = 0.f;
    #pragma unroll
    for (int j = 0; j < 4; j++) {
        const int h = tx + j * 256;
        const float2 ph = __half22float2(ph_row[h]);
        const float c = g_cP[(b * NC + ch) * H_ + h];
        const float v = fmaf(c, ph.x, ph.y);
        hv[j] = v;
        s += v;
        s2 = fmaf(v, v, s2);
    }

    __shared__ float rs[8], rs2[8];
    #pragma unroll
    for (int o = 16; o > 0; o >>= 1) {
        s  += __shfl_xor_sync(0xffffffffu, s,  o);
        s2 += __shfl_xor_sync(0xffffffffu, s2, o);
    }
    const int w = tx >> 5, l = tx & 31;
    if (l == 0) { rs[w] = s; rs2[w] = s2; }
    __syncthreads();
    if (w == 0) {
        s  = (l < 8) ? rs[l]  : 0.f;
        s2 = (l < 8) ? rs2[l] : 0.f;
        #pragma unroll
        for (int o = 4; o > 0; o >>= 1) {
            s  += __shfl_xor_sync(0xffffffffu, s,  o);
            s2 += __shfl_xor_sync(0xffffffffu, s2, o);
        }
        if (l == 0) { rs[0] = s; rs2[0] = s2; }
    }
    __syncthreads();
    const float mu  = rs[0] * (1.f / H_);
    const float var = rs2[0] * (1.f / H_) - mu * mu;
    const float rstd = rsqrtf(var + 1e-5f);

    #pragma unroll
    for (int j = 0; j < 4; j++) {
        const int h = tx + j * 256;
        g_hn[(size_t)row * H_ + h] =
            __float2half_rn(fmaf((hv[j] - mu) * rstd, ln_g[h], ln_b[h]));
    }
}

// ------------------------------- launch -------------------------------------------
extern "C" void kernel_launch(void* const* d_in, const int* in_sizes, int n_in,
                              void* d_out, int out_size)
{
    const float* x      = (const float*)d_in[0];
    const float* W_ih   = (const float*)d_in[1];
    const float* b_ih   = (const float*)d_in[2];
    const float* W_gate = (const float*)d_in[3];
    const float* b_gate = (const float*)d_in[4];
    const float* log_a  = (const float*)d_in[5];
    const float* ln_g   = (const float*)d_in[6];
    const float* ln_b   = (const float*)d_in[7];
    const float* W_out  = (const float*)d_in[8];
    const float* b_out  = (const float*)d_in[9];
    const float* W_proj = (const float*)d_in[10];
    const float* b_proj = (const float*)d_in[11];
    float* out = (float*)d_out;

    cudaFuncSetAttribute(gemm_f16, cudaFuncAttributeMaxDynamicSharedMemorySize, SMEM_BYTES);

    __half *p_xh, *p_preh, *p_hn, *p_WcatT, *p_WoutH, *p_WprojT, *p_WcT;
    float *p_bc;
    cudaGetSymbolAddress((void**)&p_xh,     g_xh);
    cudaGetSymbolAddress((void**)&p_preh,   g_preh);
    cudaGetSymbolAddress((void**)&p_hn,     g_hn);
    cudaGetSymbolAddress((void**)&p_WcatT,  g_WcatT);
    cudaGetSymbolAddress((void**)&p_WoutH,  g_WoutH);
    cudaGetSymbolAddress((void**)&p_WprojT, g_WprojT);
    cudaGetSymbolAddress((void**)&p_WcT,    g_WcT);
    cudaGetSymbolAddress((void**)&p_bc,     g_bc);

    // lazily created side streams + events (host resources only)
    static cudaStream_t s2 = nullptr, s3 = nullptr;
    static cudaEvent_t ev_fork = nullptr, ev_wc = nullptr, ev_done = nullptr;
    static cudaEvent_t ev_conv[B_], ev_g1[B_];
    if (!s2) {
        cudaStreamCreateWithFlags(&s2, cudaStreamNonBlocking);
        cudaStreamCreateWithFlags(&s3, cudaStreamNonBlocking);
        cudaEventCreateWithFlags(&ev_fork, cudaEventDisableTiming);
        cudaEventCreateWithFlags(&ev_wc,   cudaEventDisableTiming);
        cudaEventCreateWithFlags(&ev_done, cudaEventDisableTiming);
        for (int b = 0; b < B_; b++) {
            cudaEventCreateWithFlags(&ev_conv[b], cudaEventDisableTiming);
            cudaEventCreateWithFlags(&ev_g1[b],   cudaEventDisableTiming);
        }
    }

    const dim3 blk(256);
    const dim3 tblk(32, 8);
    const dim3 tg(32, 32);
    const int CONV_BLKS = (int)((size_t)T_ * D_ / 8 / 256);   // per-batch conv blocks
    const size_t XB4  = (size_t)T_ * D_ / 4;                  // float4 per batch (input)
    const size_t XB16 = (size_t)T_ * D_ / 8;                  // uint4  per batch (fp16 out)

    // fork side streams at graph entry
    cudaEventRecord(ev_fork, 0);
    cudaStreamWaitEvent(s2, ev_fork, 0);
    cudaStreamWaitEvent(s3, ev_fork, 0);

    // ---- s2: x conversions for b>=1, then the WcT weight chain ----
    for (int b = 1; b < B_; b++) {
        conv_h8<<<CONV_BLKS, blk, 0, s2>>>((const float4*)x + (size_t)b * XB4,
                                           (uint4*)p_xh + (size_t)b * XB16);   // FIXED offset
        cudaEventRecord(ev_conv[b], s2);
    }
    trans_h<<<tg, tblk, 0, s2>>>(W_proj, p_WprojT, H_, D_);
    conv_h8<<<(int)((size_t)H_*H_/8/256), blk, 0, s2>>>((const float4*)W_out, (uint4*)p_WoutH);
    bias_comb_part<<<dim3(D_/256, BCK), blk, 0, s2>>>(b_out, W_proj);
    bias_comb_final<<<D_/256, blk, 0, s2>>>(b_proj);
    gemm_f16<<<dim3(H_/BN, D_/BM), blk, SMEM_BYTES, s2>>>(p_WprojT, p_WoutH, nullptr, nullptr,
                                                          (float*)p_WcT, H_, H_, 2, nullptr, 0);
    cudaEventRecord(ev_wc, s2);

    // ---- main: weight transposes + conv(b0), then per-batch GEMM1 ----
    trans_h_il<<<tg, tblk>>>(W_ih,   p_WcatT, D_, H_, 0);
    trans_h_il<<<tg, tblk>>>(W_gate, p_WcatT, D_, H_, 1);
    conv_h8<<<CONV_BLKS, blk>>>((const float4*)x, (uint4*)p_xh);

    for (int b = 0; b < B_; b++) {
        if (b >= 1) cudaStreamWaitEvent(0, ev_conv[b], 0);
        gemm_f16<<<dim3(NPRE/BN, T_/BM), blk, SMEM_BYTES>>>(
            p_xh, p_WcatT, b_ih, b_gate, (float*)p_preh,
            D_, NPRE, 1, log_a, b * T_);
        cudaEventRecord(ev_g1[b], 0);
    }

    // ---- s3: per-batch scan2 -> fix_ln -> GEMM3, overlapping GEMM1(b+1) ----
    cudaStreamWaitEvent(s3, ev_wc, 0);
    for (int b = 0; b < B_; b++) {
        cudaStreamWaitEvent(s3, ev_g1[b], 0);
        scan_pass2<<<H_/256, blk, 0, s3>>>(b);
        fix_ln<<<T_, blk, 0, s3>>>(ln_g, ln_b, b * T_);
        gemm_f16<<<dim3(D_/BN, T_/BM), blk, SMEM_BYTES, s3>>>(
            p_hn, p_WcT, p_bc, nullptr, out, H_, D_, 0, nullptr, b * T_);
    }
    cudaEventRecord(ev_done, s3);

    // join everything on the capture stream
    cudaStreamWaitEvent(0, ev_done, 0);
}

// round 13
// speedup vs baseline: 1.1666x; 1.1666x over previous
#include <cuda_runtime.h>
#include <cuda_fp16.h>
#include <cstdint>
#include <math.h>

// Problem constants
#define B_   4
#define T_   8192
#define H_   1024
#define D_   1024
#define M_   (B_*T_)     // 32768
#define CH   128
#define NC   (T_/CH)     // 64
#define NPRE 2048
#define BCK  16

// ---------------- scratch (device globals) ------------------------------------
__device__ __half g_xh[(size_t)M_*D_];       // fp16 x
__device__ __half g_preh[(size_t)M_*NPRE];   // interleaved (P, h_local) __half2 per channel
__device__ __half g_hn[(size_t)M_*H_];       // layernormed h (fp16)
__device__ __half g_WcatT[(size_t)NPRE*D_];  // interleaved: row 2h=W_ih^T_h, 2h+1=W_gate^T_h
__device__ __half g_WoutH[(size_t)H_*H_];    // W_out fp16 row-major
__device__ __half g_WprojT[(size_t)D_*H_];   // W_proj^T fp16 [D][H]
__device__ __half g_WcT[(size_t)D_*H_];      // (W_out@W_proj)^T fp16 [D][H]
__device__ float  g_bcp[BCK*D_];
__device__ float  g_bc[D_];                  // b_out@W_proj + b_proj
__device__ float  g_cA[B_*NC*H_];
__device__ float  g_cB[B_*NC*H_];
__device__ float  g_cP[B_*NC*H_];

// ---------------- helpers -------------------------------------------------------
__device__ __forceinline__ void cp16(void* smem_dst, const void* gptr) {
    uint32_t s = (uint32_t)__cvta_generic_to_shared(smem_dst);
    asm volatile("cp.async.cg.shared.global [%0], [%1], 16;\n" :: "r"(s), "l"(gptr));
}
__device__ __forceinline__ void mma_f16(float* d, const uint32_t* a, uint32_t b0, uint32_t b1) {
    asm volatile(
        "mma.sync.aligned.m16n8k16.row.col.f32.f16.f16.f32 "
        "{%0,%1,%2,%3}, {%4,%5,%6,%7}, {%8,%9}, {%0,%1,%2,%3};\n"
        : "+f"(d[0]), "+f"(d[1]), "+f"(d[2]), "+f"(d[3])
        : "r"(a[0]), "r"(a[1]), "r"(a[2]), "r"(a[3]), "r"(b0), "r"(b1));
}
#define LDSM4(r, addr)                                                            \
    asm volatile("ldmatrix.sync.aligned.m8n8.x4.shared.b16 {%0,%1,%2,%3}, [%4];"  \
        : "=r"((r)[0]), "=r"((r)[1]), "=r"((r)[2]), "=r"((r)[3]) : "r"(addr))

// ---------------- FP16 tensor-core GEMM (R8-best config) -------------------------
// C[M,N] = A[M,K](fp16 rm) @ Bt[N,K](fp16 rm)^T + bias[N]
// mode 0: fp32 store (+bias). mode 1: fused chunk-scan epilogue (fp16 pair store).
// mode 2: fp16 store, no bias.
#define BM 128
#define BN 128
#define BK 64
#define ASTR 72
#define AS_HALFS (BM*ASTR)
#define BS_HALFS (BN*ASTR)
#define STG_HALFS (AS_HALFS+BS_HALFS)
#define STAGES 3
#define SMEM_BYTES (STAGES*STG_HALFS*2)   // 110592
#define SSTR 68

__global__ void __launch_bounds__(256, 2) gemm_f16(
    const __half* __restrict__ A, const __half* __restrict__ Bt,
    const float* __restrict__ bias, const float* __restrict__ bias2,
    float* __restrict__ C,
    int K, int N, int mode, const float* __restrict__ log_a)
{
    extern __shared__ __half smh[];

    const int tid  = threadIdx.x;
    const int lane = tid & 31;
    const int warp = tid >> 5;
    const int g    = lane >> 2;
    const int tig  = lane & 3;
    const int wm   = warp & 1;
    const int wn   = warp >> 1;
    const int row0 = blockIdx.y * BM;
    const int col0 = blockIdx.x * BN;

    float acc[4][4][4];
    #pragma unroll
    for (int i = 0; i < 4; i++)
        #pragma unroll
        for (int j = 0; j < 4; j++)
            #pragma unroll
            for (int r = 0; r < 4; r++) acc[i][j][r] = 0.f;

    const int NT = K / BK;

    const uint32_t S0 = (uint32_t)__cvta_generic_to_shared(smh);
    const uint32_t aoff = ((wm * 64 + (lane & 15)) * ASTR + (lane >> 4) * 8) * 2;
    const uint32_t boff = (AS_HALFS + (wn * 32 + (lane & 7) + (lane >> 4) * 8) * ASTR
                           + ((lane >> 3) & 1) * 8) * 2;

    auto load_tiles = [&](int st, int kt) {
        __half* As = smh + st * STG_HALFS;
        __half* Bs = As + AS_HALFS;
        const __half* gA = A  + (size_t)row0 * K + kt * BK;
        const __half* gB = Bt + (size_t)col0 * K + kt * BK;
        #pragma unroll
        for (int i = 0; i < 4; i++) {
            int idx = tid + 256 * i;
            int r = idx >> 3, c = idx & 7;
            cp16(As + r * ASTR + c * 8, gA + (size_t)r * K + c * 8);
        }
        #pragma unroll
        for (int i = 0; i < 4; i++) {
            int idx = tid + 256 * i;
            int r = idx >> 3, c = idx & 7;
            cp16(Bs + r * ASTR + c * 8, gB + (size_t)r * K + c * 8);
        }
    };

    load_tiles(0, 0);
    asm volatile("cp.async.commit_group;\n");
    load_tiles(1, 1);
    asm volatile("cp.async.commit_group;\n");
    asm volatile("cp.async.wait_group 1;\n");
    __syncthreads();

    for (int kt = 0; kt < NT; kt++) {
        if (kt + 2 < NT) load_tiles((kt + 2) % STAGES, kt + 2);
        asm volatile("cp.async.commit_group;\n");

        const int st = kt % STAGES;
        const uint32_t aBase = S0 + st * (STG_HALFS * 2) + aoff;
        const uint32_t bBase = S0 + st * (STG_HALFS * 2) + boff;
        #pragma unroll
        for (int ks = 0; ks < 4; ks++) {
            uint32_t af[4][4], bf[2][4];
            #pragma unroll
            for (int mt = 0; mt < 4; mt++)
                LDSM4(af[mt], aBase + (mt * 16 * ASTR + ks * 16) * 2);
            #pragma unroll
            for (int ntp = 0; ntp < 2; ntp++)
                LDSM4(bf[ntp], bBase + (ntp * 16 * ASTR + ks * 16) * 2);
            #pragma unroll
            for (int mt = 0; mt < 4; mt++)
                #pragma unroll
                for (int nt = 0; nt < 4; nt++)
                    mma_f16(acc[mt][nt], af[mt],
                            bf[nt >> 1][(nt & 1) * 2], bf[nt >> 1][(nt & 1) * 2 + 1]);
        }

        asm volatile("cp.async.wait_group 1;\n");
        __syncthreads();
    }

    if (mode == 0) {
        #pragma unroll
        for (int nt = 0; nt < 4; nt++) {
            int c = col0 + wn * 32 + nt * 8 + 2 * tig;
            float b0 = 0.f, b1 = 0.f;
            if (bias) { b0 = bias[c]; b1 = bias[c + 1]; }
            #pragma unroll
            for (int mt = 0; mt < 4; mt++) {
                int r = row0 + wm * 64 + mt * 16 + g;
                float2 v0 = make_float2(acc[mt][nt][0] + b0, acc[mt][nt][1] + b1);
                float2 v1 = make_float2(acc[mt][nt][2] + b0, acc[mt][nt][3] + b1);
                *(float2*)(C + (size_t)r * N + c)       = v0;
                *(float2*)(C + (size_t)(r + 8) * N + c) = v1;
            }
        }
        return;
    }

    if (mode == 2) {   // fp16 store, no bias
        __half2* Ch = (__half2*)C;
        #pragma unroll
        for (int nt = 0; nt < 4; nt++) {
            int c = col0 + wn * 32 + nt * 8 + 2 * tig;
            #pragma unroll
            for (int mt = 0; mt < 4; mt++) {
                int r = row0 + wm * 64 + mt * 16 + g;
                Ch[((size_t)r * N + c) >> 1]       = __floats2half2_rn(acc[mt][nt][0], acc[mt][nt][1]);
                Ch[((size_t)(r + 8) * N + c) >> 1] = __floats2half2_rn(acc[mt][nt][2], acc[mt][nt][3]);
            }
        }
        return;
    }

    // ---- mode 1: fused chunk-local scan epilogue (bias = b_ih, bias2 = b_gate) ----
    float* sA = (float*)smh;            // alpha [128][SSTR]
    float* sB = sA + 128 * SSTR;        // beta

    #pragma unroll
    for (int nt = 0; nt < 4; nt++) {
        const int c    = wn * 32 + nt * 8 + 2 * tig;       // local, even
        const int hloc = c >> 1;
        const int hg   = (col0 >> 1) + hloc;
        const float bi = bias[hg];
        const float bg = bias2[hg];
        const float av = expf(log_a[hg]);
        #pragma unroll
        for (int mt = 0; mt < 4; mt++) {
            const int r = wm * 64 + mt * 16 + g;
            {
                float ih = acc[mt][nt][0] + bi;
                float gp = acc[mt][nt][1] + bg;
                float gt = 1.f / (1.f + __expf(-gp));
                sA[r * SSTR + hloc] = (1.f - gt) * av;
                sB[r * SSTR + hloc] = gt * ih;
            }
            {
                float ih = acc[mt][nt][2] + bi;
                float gp = acc[mt][nt][3] + bg;
                float gt = 1.f / (1.f + __expf(-gp));
                sA[(r + 8) * SSTR + hloc] = (1.f - gt) * av;
                sB[(r + 8) * SSTR + hloc] = gt * ih;
            }
        }
    }
    __syncthreads();

    if (tid < 128) {
        const int h = tid & 63, half = tid >> 6;
        float P = 1.f, hl = 0.f;
        int base = (half * 64) * SSTR + h;
        #pragma unroll 8
        for (int i = 0; i < 64; i++, base += SSTR) {
            float al = sA[base], be = sB[base];
            P *= al;
            hl = fmaf(al, hl, be);
            sA[base] = P;
            sB[base] = hl;
        }
    }
    __syncthreads();

    const int bb  = row0 / T_;
    const int chh = (row0 - bb * T_) >> 7;
    __half2* Ch = (__half2*)C;
    #pragma unroll
    for (int k = 0; k < 32; k++) {
        const int e = tid + 256 * k;
        const int t = e >> 6, h = e & 63;
        float P  = sA[t * SSTR + h];
        float hl = sB[t * SSTR + h];
        if (t >= 64) {
            const float Pm = sA[63 * SSTR + h];
            const float hm = sB[63 * SSTR + h];
            hl = fmaf(P, hm, hl);
            P  = P * Pm;
        }
        const int hg = (col0 >> 1) + h;
        Ch[(size_t)(row0 + t) * (NPRE / 2) + hg] = __floats2half2_rn(P, hl);
        if (t == 127) {
            const int ci = (bb * NC + chh) * H_ + hg;
            g_cA[ci] = P;
            g_cB[ci] = hl;
        }
    }
}

// ---------------- pre-passes -----------------------------------------------------
__global__ void __launch_bounds__(256) conv_h8(const float4* __restrict__ in,
                                               uint4* __restrict__ out)
{
    const size_t i = (size_t)blockIdx.x * 256 + threadIdx.x;
    float4 v0 = in[2 * i], v1 = in[2 * i + 1];
    __half2 h0 = __floats2half2_rn(v0.x, v0.y);
    __half2 h1 = __floats2half2_rn(v0.z, v0.w);
    __half2 h2 = __floats2half2_rn(v1.x, v1.y);
    __half2 h3 = __floats2half2_rn(v1.z, v1.w);
    uint4 o;
    o.x = *(uint32_t*)&h0; o.y = *(uint32_t*)&h1;
    o.z = *(uint32_t*)&h2; o.w = *(uint32_t*)&h3;
    out[i] = o;
}

// out[C][R] = fp16(in[R][C]^T)
__global__ void __launch_bounds__(256) trans_h(const float* __restrict__ in,
                                               __half* __restrict__ out,
                                               int R, int C)
{
    __shared__ float t[32][33];
    int bx = blockIdx.x * 32, by = blockIdx.y * 32;
    #pragma unroll
    for (int j = 0; j < 32; j += 8)
        t[threadIdx.y + j][threadIdx.x] =
            in[(size_t)(by + threadIdx.y + j) * C + bx + threadIdx.x];
    __syncthreads();
    #pragma unroll
    for (int j = 0; j < 32; j += 8)
        out[(size_t)(bx + threadIdx.y + j) * R + by + threadIdx.x] =
            __float2half_rn(t[threadIdx.x][threadIdx.y + j]);
}

// interleaved transpose: out[2*col + sel][row] = fp16(in[row][col]); in [R][C]
__global__ void __launch_bounds__(256) trans_h_il(const float* __restrict__ in,
                                                  __half* __restrict__ out,
                                                  int R, int C, int sel)
{
    __shared__ float t[32][33];
    int bx = blockIdx.x * 32, by = blockIdx.y * 32;
    #pragma unroll
    for (int j = 0; j < 32; j += 8)
        t[threadIdx.y + j][threadIdx.x] =
            in[(size_t)(by + threadIdx.y + j) * C + bx + threadIdx.x];
    __syncthreads();
    #pragma unroll
    for (int j = 0; j < 32; j += 8)
        out[(size_t)(2 * (bx + threadIdx.y + j) + sel) * R + by + threadIdx.x] =
            __float2half_rn(t[threadIdx.x][threadIdx.y + j]);
}

__global__ void __launch_bounds__(256) bias_comb_part(const float* __restrict__ b_out,
                                                      const float* __restrict__ W_proj)
{
    const int d = blockIdx.x * 256 + threadIdx.x;
    const int p = blockIdx.y;
    float acc = 0.f;
    #pragma unroll 8
    for (int hh = p * 64; hh < p * 64 + 64; hh++)
        acc = fmaf(b_out[hh], W_proj[(size_t)hh * D_ + d], acc);
    g_bcp[p * D_ + d] = acc;
}
__global__ void __launch_bounds__(256) bias_comb_final(const float* __restrict__ b_proj)
{
    const int d = blockIdx.x * 256 + threadIdx.x;
    float acc = b_proj[d];
    #pragma unroll
    for (int p = 0; p < BCK; p++) acc += g_bcp[p * D_ + d];
    g_bc[d] = acc;
}

// ---------------- scan pass 2: scan chunk carries --------------------------------
__global__ void __launch_bounds__(256) scan_pass2()
{
    const int idx = blockIdx.x * 256 + threadIdx.x;
    const int b = idx / H_, h = idx - b * H_;
    float c = 0.f;
    #pragma unroll 4
    for (int ch = 0; ch < NC; ch++) {
        const int i = (b * NC + ch) * H_ + h;
        g_cP[i] = c;
        c = fmaf(g_cA[i], c, g_cB[i]);
    }
}

// ---------------- pass 3: carry fix-up + LayerNorm (fp16 in/out) -----------------
__global__ void __launch_bounds__(256) fix_ln(const float* __restrict__ ln_g,
                                              const float* __restrict__ ln_b)
{
    const int row = blockIdx.x;
    const int b = row / T_, t = row - b * T_;
    const int ch = t / CH;
    const int tx = threadIdx.x;
    const __half2* ph_row = (const __half2*)g_preh + (size_t)row * (NPRE / 2);

    float hv[4];
    float s = 0.f, s2 = 0.f;
    #pragma unroll
    for (int j = 0; j < 4; j++) {
        const int h = tx + j * 256;
        const float2 ph = __half22float2(ph_row[h]);
        const float c = g_cP[(b * NC + ch) * H_ + h];
        const float v = fmaf(c, ph.x, ph.y);
        hv[j] = v;
        s += v;
        s2 = fmaf(v, v, s2);
    }

    __shared__ float rs[8], rs2[8];
    #pragma unroll
    for (int o = 16; o > 0; o >>= 1) {
        s  += __shfl_xor_sync(0xffffffffu, s,  o);
        s2 += __shfl_xor_sync(0xffffffffu, s2, o);
    }
    const int w = tx >> 5, l = tx & 31;
    if (l == 0) { rs[w] = s; rs2[w] = s2; }
    __syncthreads();
    if (w == 0) {
        s  = (l < 8) ? rs[l]  : 0.f;
        s2 = (l < 8) ? rs2[l] : 0.f;
        #pragma unroll
        for (int o = 4; o > 0; o >>= 1) {
            s  += __shfl_xor_sync(0xffffffffu, s,  o);
            s2 += __shfl_xor_sync(0xffffffffu, s2, o);
        }
        if (l == 0) { rs[0] = s; rs2[0] = s2; }
    }
    __syncthreads();
    const float mu  = rs[0] * (1.f / H_);
    const float var = rs2[0] * (1.f / H_) - mu * mu;
    const float rstd = rsqrtf(var + 1e-5f);

    #pragma unroll
    for (int j = 0; j < 4; j++) {
        const int h = tx + j * 256;
        g_hn[(size_t)row * H_ + h] =
            __float2half_rn(fmaf((hv[j] - mu) * rstd, ln_g[h], ln_b[h]));
    }
}

// ------------------------------- launch -------------------------------------------
extern "C" void kernel_launch(void* const* d_in, const int* in_sizes, int n_in,
                              void* d_out, int out_size)
{
    const float* x      = (const float*)d_in[0];
    const float* W_ih   = (const float*)d_in[1];
    const float* b_ih   = (const float*)d_in[2];
    const float* W_gate = (const float*)d_in[3];
    const float* b_gate = (const float*)d_in[4];
    const float* log_a  = (const float*)d_in[5];
    const float* ln_g   = (const float*)d_in[6];
    const float* ln_b   = (const float*)d_in[7];
    const float* W_out  = (const float*)d_in[8];
    const float* b_out  = (const float*)d_in[9];
    const float* W_proj = (const float*)d_in[10];
    const float* b_proj = (const float*)d_in[11];
    float* out = (float*)d_out;

    cudaFuncSetAttribute(gemm_f16, cudaFuncAttributeMaxDynamicSharedMemorySize, SMEM_BYTES);

    __half *p_xh, *p_preh, *p_hn, *p_WcatT, *p_WoutH, *p_WprojT, *p_WcT;
    float *p_bc;
    cudaGetSymbolAddress((void**)&p_xh,     g_xh);
    cudaGetSymbolAddress((void**)&p_preh,   g_preh);
    cudaGetSymbolAddress((void**)&p_hn,     g_hn);
    cudaGetSymbolAddress((void**)&p_WcatT,  g_WcatT);
    cudaGetSymbolAddress((void**)&p_WoutH,  g_WoutH);
    cudaGetSymbolAddress((void**)&p_WprojT, g_WprojT);
    cudaGetSymbolAddress((void**)&p_WcT,    g_WcT);
    cudaGetSymbolAddress((void**)&p_bc,     g_bc);

    // lazily created side stream + events (host resources only)
    static cudaStream_t s2 = nullptr;
    static cudaEvent_t ev_fork = nullptr, ev_x = nullptr, ev_wc = nullptr;
    if (!s2) {
        cudaStreamCreateWithFlags(&s2, cudaStreamNonBlocking);
        cudaEventCreateWithFlags(&ev_fork, cudaEventDisableTiming);
        cudaEventCreateWithFlags(&ev_x,    cudaEventDisableTiming);
        cudaEventCreateWithFlags(&ev_wc,   cudaEventDisableTiming);
    }

    const dim3 blk(256);
    const dim3 tblk(32, 8);
    const dim3 tg(32, 32);

    // fork side stream at graph entry
    cudaEventRecord(ev_fork, 0);
    cudaStreamWaitEvent(s2, ev_fork, 0);

    // ---- s2: x fp16 conversion (overlaps main's weight transposes), then Wc chain
    conv_h8<<<(int)((size_t)M_*D_/8/256), blk, 0, s2>>>((const float4*)x, (uint4*)p_xh);
    cudaEventRecord(ev_x, s2);
    trans_h<<<tg, tblk, 0, s2>>>(W_proj, p_WprojT, H_, D_);
    conv_h8<<<(int)((size_t)H_*H_/8/256), blk, 0, s2>>>((const float4*)W_out, (uint4*)p_WoutH);
    bias_comb_part<<<dim3(D_/256, BCK), blk, 0, s2>>>(b_out, W_proj);
    bias_comb_final<<<D_/256, blk, 0, s2>>>(b_proj);
    // WcT = Wproj^T @ Wout^T  (== (Wout@Wproj)^T), stored fp16 directly
    gemm_f16<<<dim3(H_/BN, D_/BM), blk, SMEM_BYTES, s2>>>(p_WprojT, p_WoutH, nullptr, nullptr,
                                                          (float*)p_WcT, H_, H_, 2, nullptr);
    cudaEventRecord(ev_wc, s2);

    // ---- main stream: weight transposes, then the big fused GEMM ----
    trans_h_il<<<tg, tblk>>>(W_ih,   p_WcatT, D_, H_, 0);
    trans_h_il<<<tg, tblk>>>(W_gate, p_WcatT, D_, H_, 1);
    cudaStreamWaitEvent(0, ev_x, 0);

    // fused [ih|gate] GEMM + in-epilogue chunk scan -> g_preh holds (P, h_local)
    gemm_f16<<<dim3(NPRE/BN, M_/BM), blk, SMEM_BYTES>>>(p_xh, p_WcatT, b_ih, b_gate,
                                                        (float*)p_preh, D_, NPRE, 1, log_a);

    // carry scan + layernorm
    scan_pass2<<<(B_*H_)/256, blk>>>();
    fix_ln<<<M_, blk>>>(ln_g, ln_b);

    // join side stream, then final GEMM: out = hn @ Wc + bc
    cudaStreamWaitEvent(0, ev_wc, 0);
    gemm_f16<<<dim3(D_/BN, M_/BM), blk, SMEM_BYTES>>>(p_hn, p_WcT, p_bc, nullptr, out,
                                                      H_, D_, 0, nullptr);
}

// round 14
// speedup vs baseline: 1.1816x; 1.0129x over previous
#include <cuda_runtime.h>
#include <cuda_fp16.h>
#include <cstdint>
#include <math.h>

// Problem constants
#define B_   4
#define T_   8192
#define H_   1024
#define D_   1024
#define M_   (B_*T_)     // 32768
#define CH   128
#define NC   (T_/CH)     // 64
#define NPRE 2048
#define BCK  16
#define NCOLB (NPRE/128) // 16 col-blocks in GEMM1

// ---------------- scratch (device globals) ------------------------------------
__device__ __half g_xh[(size_t)M_*D_];       // fp16 x
__device__ __half g_preh[(size_t)M_*NPRE];   // interleaved (P, h_local) __half2 per channel
__device__ __half g_hn[(size_t)M_*H_];       // layernormed h (fp16)
__device__ __half g_WcatT[(size_t)NPRE*D_];  // interleaved: row 2h=W_ih^T_h, 2h+1=W_gate^T_h
__device__ __half g_WoutH[(size_t)H_*H_];    // W_out fp16 row-major
__device__ __half g_WprojT[(size_t)D_*H_];   // W_proj^T fp16 [D][H]
__device__ __half g_WcT[(size_t)D_*H_];      // (W_out@W_proj)^T fp16 [D][H]
__device__ float  g_bcp[BCK*D_];
__device__ float  g_bc[D_];                  // b_out@W_proj + b_proj
__device__ float  g_cA[B_*NC*H_];
__device__ float  g_cB[B_*NC*H_];
__device__ float  g_cP[B_*NC*H_];
__device__ int    g_cnt[B_*NCOLB];           // carry-scan completion counters (self-resetting)

// ---------------- helpers -------------------------------------------------------
__device__ __forceinline__ void cp16(void* smem_dst, const void* gptr) {
    uint32_t s = (uint32_t)__cvta_generic_to_shared(smem_dst);
    asm volatile("cp.async.cg.shared.global [%0], [%1], 16;\n" :: "r"(s), "l"(gptr));
}
__device__ __forceinline__ void mma_f16(float* d, const uint32_t* a, uint32_t b0, uint32_t b1) {
    asm volatile(
        "mma.sync.aligned.m16n8k16.row.col.f32.f16.f16.f32 "
        "{%0,%1,%2,%3}, {%4,%5,%6,%7}, {%8,%9}, {%0,%1,%2,%3};\n"
        : "+f"(d[0]), "+f"(d[1]), "+f"(d[2]), "+f"(d[3])
        : "r"(a[0]), "r"(a[1]), "r"(a[2]), "r"(a[3]), "r"(b0), "r"(b1));
}
#define LDSM4(r, addr)                                                            \
    asm volatile("ldmatrix.sync.aligned.m8n8.x4.shared.b16 {%0,%1,%2,%3}, [%4];"  \
        : "=r"((r)[0]), "=r"((r)[1]), "=r"((r)[2]), "=r"((r)[3]) : "r"(addr))

// ---------------- FP16 tensor-core GEMM (R8-best config) -------------------------
// C[M,N] = A[M,K](fp16 rm) @ Bt[N,K](fp16 rm)^T + bias[N]
// mode 0: fp32 store (+bias). mode 1: fused chunk-scan epilogue (fp16 pair store)
//         + last-block-per-(batch,colblk) carry scan (replaces scan_pass2).
// mode 2: fp16 store, no bias.
#define BM 128
#define BN 128
#define BK 64
#define ASTR 72
#define AS_HALFS (BM*ASTR)
#define BS_HALFS (BN*ASTR)
#define STG_HALFS (AS_HALFS+BS_HALFS)
#define STAGES 3
#define SMEM_BYTES (STAGES*STG_HALFS*2)   // 110592
#define SSTR 68

__global__ void __launch_bounds__(256, 2) gemm_f16(
    const __half* __restrict__ A, const __half* __restrict__ Bt,
    const float* __restrict__ bias, const float* __restrict__ bias2,
    float* __restrict__ C,
    int K, int N, int mode, const float* __restrict__ log_a)
{
    extern __shared__ __half smh[];

    const int tid  = threadIdx.x;
    const int lane = tid & 31;
    const int warp = tid >> 5;
    const int g    = lane >> 2;
    const int tig  = lane & 3;
    const int wm   = warp & 1;
    const int wn   = warp >> 1;
    const int row0 = blockIdx.y * BM;
    const int col0 = blockIdx.x * BN;

    float acc[4][4][4];
    #pragma unroll
    for (int i = 0; i < 4; i++)
        #pragma unroll
        for (int j = 0; j < 4; j++)
            #pragma unroll
            for (int r = 0; r < 4; r++) acc[i][j][r] = 0.f;

    const int NT = K / BK;

    const uint32_t S0 = (uint32_t)__cvta_generic_to_shared(smh);
    const uint32_t aoff = ((wm * 64 + (lane & 15)) * ASTR + (lane >> 4) * 8) * 2;
    const uint32_t boff = (AS_HALFS + (wn * 32 + (lane & 7) + (lane >> 4) * 8) * ASTR
                           + ((lane >> 3) & 1) * 8) * 2;

    auto load_tiles = [&](int st, int kt) {
        __half* As = smh + st * STG_HALFS;
        __half* Bs = As + AS_HALFS;
        const __half* gA = A  + (size_t)row0 * K + kt * BK;
        const __half* gB = Bt + (size_t)col0 * K + kt * BK;
        #pragma unroll
        for (int i = 0; i < 4; i++) {
            int idx = tid + 256 * i;
            int r = idx >> 3, c = idx & 7;
            cp16(As + r * ASTR + c * 8, gA + (size_t)r * K + c * 8);
        }
        #pragma unroll
        for (int i = 0; i < 4; i++) {
            int idx = tid + 256 * i;
            int r = idx >> 3, c = idx & 7;
            cp16(Bs + r * ASTR + c * 8, gB + (size_t)r * K + c * 8);
        }
    };

    load_tiles(0, 0);
    asm volatile("cp.async.commit_group;\n");
    load_tiles(1, 1);
    asm volatile("cp.async.commit_group;\n");
    asm volatile("cp.async.wait_group 1;\n");
    __syncthreads();

    for (int kt = 0; kt < NT; kt++) {
        if (kt + 2 < NT) load_tiles((kt + 2) % STAGES, kt + 2);
        asm volatile("cp.async.commit_group;\n");

        const int st = kt % STAGES;
        const uint32_t aBase = S0 + st * (STG_HALFS * 2) + aoff;
        const uint32_t bBase = S0 + st * (STG_HALFS * 2) + boff;
        #pragma unroll
        for (int ks = 0; ks < 4; ks++) {
            uint32_t af[4][4], bf[2][4];
            #pragma unroll
            for (int mt = 0; mt < 4; mt++)
                LDSM4(af[mt], aBase + (mt * 16 * ASTR + ks * 16) * 2);
            #pragma unroll
            for (int ntp = 0; ntp < 2; ntp++)
                LDSM4(bf[ntp], bBase + (ntp * 16 * ASTR + ks * 16) * 2);
            #pragma unroll
            for (int mt = 0; mt < 4; mt++)
                #pragma unroll
                for (int nt = 0; nt < 4; nt++)
                    mma_f16(acc[mt][nt], af[mt],
                            bf[nt >> 1][(nt & 1) * 2], bf[nt >> 1][(nt & 1) * 2 + 1]);
        }

        asm volatile("cp.async.wait_group 1;\n");
        __syncthreads();
    }

    if (mode == 0) {
        #pragma unroll
        for (int nt = 0; nt < 4; nt++) {
            int c = col0 + wn * 32 + nt * 8 + 2 * tig;
            float b0 = 0.f, b1 = 0.f;
            if (bias) { b0 = bias[c]; b1 = bias[c + 1]; }
            #pragma unroll
            for (int mt = 0; mt < 4; mt++) {
                int r = row0 + wm * 64 + mt * 16 + g;
                float2 v0 = make_float2(acc[mt][nt][0] + b0, acc[mt][nt][1] + b1);
                float2 v1 = make_float2(acc[mt][nt][2] + b0, acc[mt][nt][3] + b1);
                *(float2*)(C + (size_t)r * N + c)       = v0;
                *(float2*)(C + (size_t)(r + 8) * N + c) = v1;
            }
        }
        return;
    }

    if (mode == 2) {   // fp16 store, no bias
        __half2* Ch = (__half2*)C;
        #pragma unroll
        for (int nt = 0; nt < 4; nt++) {
            int c = col0 + wn * 32 + nt * 8 + 2 * tig;
            #pragma unroll
            for (int mt = 0; mt < 4; mt++) {
                int r = row0 + wm * 64 + mt * 16 + g;
                Ch[((size_t)r * N + c) >> 1]       = __floats2half2_rn(acc[mt][nt][0], acc[mt][nt][1]);
                Ch[((size_t)(r + 8) * N + c) >> 1] = __floats2half2_rn(acc[mt][nt][2], acc[mt][nt][3]);
            }
        }
        return;
    }

    // ---- mode 1: fused chunk-local scan epilogue (bias = b_ih, bias2 = b_gate) ----
    float* sA = (float*)smh;            // alpha [128][SSTR]
    float* sB = sA + 128 * SSTR;        // beta

    #pragma unroll
    for (int nt = 0; nt < 4; nt++) {
        const int c    = wn * 32 + nt * 8 + 2 * tig;       // local, even
        const int hloc = c >> 1;
        const int hg   = (col0 >> 1) + hloc;
        const float bi = bias[hg];
        const float bg = bias2[hg];
        const float av = expf(log_a[hg]);
        #pragma unroll
        for (int mt = 0; mt < 4; mt++) {
            const int r = wm * 64 + mt * 16 + g;
            {
                float ih = acc[mt][nt][0] + bi;
                float gp = acc[mt][nt][1] + bg;
                float gt = 1.f / (1.f + __expf(-gp));
                sA[r * SSTR + hloc] = (1.f - gt) * av;
                sB[r * SSTR + hloc] = gt * ih;
            }
            {
                float ih = acc[mt][nt][2] + bi;
                float gp = acc[mt][nt][3] + bg;
                float gt = 1.f / (1.f + __expf(-gp));
                sA[(r + 8) * SSTR + hloc] = (1.f - gt) * av;
                sB[(r + 8) * SSTR + hloc] = gt * ih;
            }
        }
    }
    __syncthreads();

    if (tid < 128) {
        const int h = tid & 63, half = tid >> 6;
        float P = 1.f, hl = 0.f;
        int base = (half * 64) * SSTR + h;
        #pragma unroll 8
        for (int i = 0; i < 64; i++, base += SSTR) {
            float al = sA[base], be = sB[base];
            P *= al;
            hl = fmaf(al, hl, be);
            sA[base] = P;
            sB[base] = hl;
        }
    }
    __syncthreads();

    const int bb  = row0 / T_;
    const int chh = (row0 - bb * T_) >> 7;
    __half2* Ch = (__half2*)C;
    #pragma unroll
    for (int k = 0; k < 32; k++) {
        const int e = tid + 256 * k;
        const int t = e >> 6, h = e & 63;
        float P  = sA[t * SSTR + h];
        float hl = sB[t * SSTR + h];
        if (t >= 64) {
            const float Pm = sA[63 * SSTR + h];
            const float hm = sB[63 * SSTR + h];
            hl = fmaf(P, hm, hl);
            P  = P * Pm;
        }
        const int hg = (col0 >> 1) + h;
        Ch[(size_t)(row0 + t) * (NPRE / 2) + hg] = __floats2half2_rn(P, hl);
        if (t == 127) {
            const int ci = (bb * NC + chh) * H_ + hg;
            g_cA[ci] = P;
            g_cB[ci] = hl;
        }
    }

    // ---- last-block-per-(batch, colblk) carry scan (replaces scan_pass2) ----
    __shared__ int s_last;
    __threadfence();          // make this block's g_cA/g_cB visible device-wide
    __syncthreads();
    if (tid == 0) {
        int prev = atomicAdd(&g_cnt[bb * NCOLB + blockIdx.x], 1);
        s_last = (prev == NC - 1) ? 1 : 0;
    }
    __syncthreads();
    if (s_last) {
        __threadfence();      // ensure we observe all other blocks' carry writes
        if (tid < 64) {
            const int hg = (col0 >> 1) + tid;
            float c = 0.f;
            #pragma unroll 4
            for (int ch = 0; ch < NC; ch++) {
                const int i = (bb * NC + ch) * H_ + hg;
                g_cP[i] = c;
                c = fmaf(g_cA[i], c, g_cB[i]);
            }
        }
        if (tid == 0) g_cnt[bb * NCOLB + blockIdx.x] = 0;   // self-reset for graph replay
    }
}

// ---------------- pre-passes -----------------------------------------------------
__global__ void __launch_bounds__(256) conv_h8(const float4* __restrict__ in,
                                               uint4* __restrict__ out)
{
    const size_t i = (size_t)blockIdx.x * 256 + threadIdx.x;
    float4 v0 = in[2 * i], v1 = in[2 * i + 1];
    __half2 h0 = __floats2half2_rn(v0.x, v0.y);
    __half2 h1 = __floats2half2_rn(v0.z, v0.w);
    __half2 h2 = __floats2half2_rn(v1.x, v1.y);
    __half2 h3 = __floats2half2_rn(v1.z, v1.w);
    uint4 o;
    o.x = *(uint32_t*)&h0; o.y = *(uint32_t*)&h1;
    o.z = *(uint32_t*)&h2; o.w = *(uint32_t*)&h3;
    out[i] = o;
}

// out[C][R] = fp16(in[R][C]^T)
__global__ void __launch_bounds__(256) trans_h(const float* __restrict__ in,
                                               __half* __restrict__ out,
                                               int R, int C)
{
    __shared__ float t[32][33];
    int bx = blockIdx.x * 32, by = blockIdx.y * 32;
    #pragma unroll
    for (int j = 0; j < 32; j += 8)
        t[threadIdx.y + j][threadIdx.x] =
            in[(size_t)(by + threadIdx.y + j) * C + bx + threadIdx.x];
    __syncthreads();
    #pragma unroll
    for (int j = 0; j < 32; j += 8)
        out[(size_t)(bx + threadIdx.y + j) * R + by + threadIdx.x] =
            __float2half_rn(t[threadIdx.x][threadIdx.y + j]);
}

// interleaved transpose: out[2*col + sel][row] = fp16(in[row][col]); in [R][C]
__global__ void __launch_bounds__(256) trans_h_il(const float* __restrict__ in,
                                                  __half* __restrict__ out,
                                                  int R, int C, int sel)
{
    __shared__ float t[32][33];
    int bx = blockIdx.x * 32, by = blockIdx.y * 32;
    #pragma unroll
    for (int j = 0; j < 32; j += 8)
        t[threadIdx.y + j][threadIdx.x] =
            in[(size_t)(by + threadIdx.y + j) * C + bx + threadIdx.x];
    __syncthreads();
    #pragma unroll
    for (int j = 0; j < 32; j += 8)
        out[(size_t)(2 * (bx + threadIdx.y + j) + sel) * R + by + threadIdx.x] =
            __float2half_rn(t[threadIdx.x][threadIdx.y + j]);
}

__global__ void __launch_bounds__(256) bias_comb_part(const float* __restrict__ b_out,
                                                      const float* __restrict__ W_proj)
{
    const int d = blockIdx.x * 256 + threadIdx.x;
    const int p = blockIdx.y;
    float acc = 0.f;
    #pragma unroll 8
    for (int hh = p * 64; hh < p * 64 + 64; hh++)
        acc = fmaf(b_out[hh], W_proj[(size_t)hh * D_ + d], acc);
    g_bcp[p * D_ + d] = acc;
}
__global__ void __launch_bounds__(256) bias_comb_final(const float* __restrict__ b_proj)
{
    const int d = blockIdx.x * 256 + threadIdx.x;
    float acc = b_proj[d];
    #pragma unroll
    for (int p = 0; p < BCK; p++) acc += g_bcp[p * D_ + d];
    g_bc[d] = acc;
}

// ---------------- carry fix-up + LayerNorm (fp16 in/out) -------------------------
__global__ void __launch_bounds__(256) fix_ln(const float* __restrict__ ln_g,
                                              const float* __restrict__ ln_b)
{
    const int row = blockIdx.x;
    const int b = row / T_, t = row - b * T_;
    const int ch = t / CH;
    const int tx = threadIdx.x;
    const __half2* ph_row = (const __half2*)g_preh + (size_t)row * (NPRE / 2);

    float hv[4];
    float s = 0.f, s2 = 0.f;
    #pragma unroll
    for (int j = 0; j < 4; j++) {
        const int h = tx + j * 256;
        const float2 ph = __half22float2(ph_row[h]);
        const float c = g_cP[(b * NC + ch) * H_ + h];
        const float v = fmaf(c, ph.x, ph.y);
        hv[j] = v;
        s += v;
        s2 = fmaf(v, v, s2);
    }

    __shared__ float rs[8], rs2[8];
    #pragma unroll
    for (int o = 16; o > 0; o >>= 1) {
        s  += __shfl_xor_sync(0xffffffffu, s,  o);
        s2 += __shfl_xor_sync(0xffffffffu, s2, o);
    }
    const int w = tx >> 5, l = tx & 31;
    if (l == 0) { rs[w] = s; rs2[w] = s2; }
    __syncthreads();
    if (w == 0) {
        s  = (l < 8) ? rs[l]  : 0.f;
        s2 = (l < 8) ? rs2[l] : 0.f;
        #pragma unroll
        for (int o = 4; o > 0; o >>= 1) {
            s  += __shfl_xor_sync(0xffffffffu, s,  o);
            s2 += __shfl_xor_sync(0xffffffffu, s2, o);
        }
        if (l == 0) { rs[0] = s; rs2[0] = s2; }
    }
    __syncthreads();
    const float mu  = rs[0] * (1.f / H_);
    const float var = rs2[0] * (1.f / H_) - mu * mu;
    const float rstd = rsqrtf(var + 1e-5f);

    #pragma unroll
    for (int j = 0; j < 4; j++) {
        const int h = tx + j * 256;
        g_hn[(size_t)row * H_ + h] =
            __float2half_rn(fmaf((hv[j] - mu) * rstd, ln_g[h], ln_b[h]));
    }
}

// ------------------------------- launch -------------------------------------------
extern "C" void kernel_launch(void* const* d_in, const int* in_sizes, int n_in,
                              void* d_out, int out_size)
{
    const float* x      = (const float*)d_in[0];
    const float* W_ih   = (const float*)d_in[1];
    const float* b_ih   = (const float*)d_in[2];
    const float* W_gate = (const float*)d_in[3];
    const float* b_gate = (const float*)d_in[4];
    const float* log_a  = (const float*)d_in[5];
    const float* ln_g   = (const float*)d_in[6];
    const float* ln_b   = (const float*)d_in[7];
    const float* W_out  = (const float*)d_in[8];
    const float* b_out  = (const float*)d_in[9];
    const float* W_proj = (const float*)d_in[10];
    const float* b_proj = (const float*)d_in[11];
    float* out = (float*)d_out;

    cudaFuncSetAttribute(gemm_f16, cudaFuncAttributeMaxDynamicSharedMemorySize, SMEM_BYTES);

    __half *p_xh, *p_preh, *p_hn, *p_WcatT, *p_WoutH, *p_WprojT, *p_WcT;
    float *p_bc;
    cudaGetSymbolAddress((void**)&p_xh,     g_xh);
    cudaGetSymbolAddress((void**)&p_preh,   g_preh);
    cudaGetSymbolAddress((void**)&p_hn,     g_hn);
    cudaGetSymbolAddress((void**)&p_WcatT,  g_WcatT);
    cudaGetSymbolAddress((void**)&p_WoutH,  g_WoutH);
    cudaGetSymbolAddress((void**)&p_WprojT, g_WprojT);
    cudaGetSymbolAddress((void**)&p_WcT,    g_WcT);
    cudaGetSymbolAddress((void**)&p_bc,     g_bc);

    // lazily created side stream + events (host resources only)
    static cudaStream_t s2 = nullptr;
    static cudaEvent_t ev_fork = nullptr, ev_x = nullptr, ev_wc = nullptr;
    if (!s2) {
        cudaStreamCreateWithFlags(&s2, cudaStreamNonBlocking);
        cudaEventCreateWithFlags(&ev_fork, cudaEventDisableTiming);
        cudaEventCreateWithFlags(&ev_x,    cudaEventDisableTiming);
        cudaEventCreateWithFlags(&ev_wc,   cudaEventDisableTiming);
    }

    const dim3 blk(256);
    const dim3 tblk(32, 8);
    const dim3 tg(32, 32);

    // fork side stream at graph entry
    cudaEventRecord(ev_fork, 0);
    cudaStreamWaitEvent(s2, ev_fork, 0);

    // ---- s2: x fp16 conversion (overlaps main's weight transposes), then Wc chain
    conv_h8<<<(int)((size_t)M_*D_/8/256), blk, 0, s2>>>((const float4*)x, (uint4*)p_xh);
    cudaEventRecord(ev_x, s2);
    trans_h<<<tg, tblk, 0, s2>>>(W_proj, p_WprojT, H_, D_);
    conv_h8<<<(int)((size_t)H_*H_/8/256), blk, 0, s2>>>((const float4*)W_out, (uint4*)p_WoutH);
    bias_comb_part<<<dim3(D_/256, BCK), blk, 0, s2>>>(b_out, W_proj);
    bias_comb_final<<<D_/256, blk, 0, s2>>>(b_proj);
    // WcT = Wproj^T @ Wout^T  (== (Wout@Wproj)^T), stored fp16 directly
    gemm_f16<<<dim3(H_/BN, D_/BM), blk, SMEM_BYTES, s2>>>(p_WprojT, p_WoutH, nullptr, nullptr,
                                                          (float*)p_WcT, H_, H_, 2, nullptr);
    cudaEventRecord(ev_wc, s2);

    // ---- main stream: weight transposes, then the big fused GEMM ----
    trans_h_il<<<tg, tblk>>>(W_ih,   p_WcatT, D_, H_, 0);
    trans_h_il<<<tg, tblk>>>(W_gate, p_WcatT, D_, H_, 1);
    cudaStreamWaitEvent(0, ev_x, 0);

    // fused [ih|gate] GEMM + chunk scan + in-kernel carry scan (last-block pattern)
    gemm_f16<<<dim3(NPRE/BN, M_/BM), blk, SMEM_BYTES>>>(p_xh, p_WcatT, b_ih, b_gate,
                                                        (float*)p_preh, D_, NPRE, 1, log_a);

    // carry fix-up + layernorm (g_cP fully written inside GEMM1)
    fix_ln<<<M_, blk>>>(ln_g, ln_b);

    // join side stream, then final GEMM: out = hn @ Wc + bc
    cudaStreamWaitEvent(0, ev_wc, 0);
    gemm_f16<<<dim3(D_/BN, M_/BM), blk, SMEM_BYTES>>>(p_hn, p_WcT, p_bc, nullptr, out,
                                                      H_, D_, 0, nullptr);
}

// round 15
// speedup vs baseline: 1.1851x; 1.0029x over previous
#include <cuda_runtime.h>
#include <cuda_fp16.h>
#include <cstdint>
#include <math.h>

// Problem constants
#define B_   4
#define T_   8192
#define H_   1024
#define D_   1024
#define M_   (B_*T_)     // 32768
#define CH   128
#define NC   (T_/CH)     // 64
#define NPRE 2048
#define BCK  16
#define NCOLB (NPRE/128) // 16 col-blocks in GEMM1

// ---------------- scratch (device globals) ------------------------------------
__device__ __half g_xh[(size_t)M_*D_];       // fp16 x
__device__ __half g_preh[(size_t)M_*NPRE];   // interleaved (P, h_local) __half2 per channel
__device__ __half g_hn[(size_t)M_*H_];       // layernormed h (fp16)
__device__ __half g_WcatT[(size_t)NPRE*D_];  // interleaved: row 2h=W_ih^T_h, 2h+1=W_gate^T_h
__device__ __half g_WoutH[(size_t)H_*H_];    // W_out fp16 row-major
__device__ __half g_WprojT[(size_t)D_*H_];   // W_proj^T fp16 [D][H]
__device__ __half g_WcT[(size_t)D_*H_];      // (W_out@W_proj)^T fp16 [D][H]
__device__ float  g_bcp[BCK*D_];
__device__ float  g_bc[D_];                  // b_out@W_proj + b_proj
__device__ float  g_cA[B_*NC*H_];
__device__ float  g_cB[B_*NC*H_];
__device__ float  g_cP[B_*NC*H_];
__device__ int    g_cnt[B_*NCOLB];           // carry-scan completion counters (self-resetting)

// ---------------- helpers -------------------------------------------------------
__device__ __forceinline__ void cp16(void* smem_dst, const void* gptr) {
    uint32_t s = (uint32_t)__cvta_generic_to_shared(smem_dst);
    asm volatile("cp.async.cg.shared.global [%0], [%1], 16;\n" :: "r"(s), "l"(gptr));
}
__device__ __forceinline__ void mma_f16(float* d, const uint32_t* a, uint32_t b0, uint32_t b1) {
    asm volatile(
        "mma.sync.aligned.m16n8k16.row.col.f32.f16.f16.f32 "
        "{%0,%1,%2,%3}, {%4,%5,%6,%7}, {%8,%9}, {%0,%1,%2,%3};\n"
        : "+f"(d[0]), "+f"(d[1]), "+f"(d[2]), "+f"(d[3])
        : "r"(a[0]), "r"(a[1]), "r"(a[2]), "r"(a[3]), "r"(b0), "r"(b1));
}
#define LDSM4(r, addr)                                                            \
    asm volatile("ldmatrix.sync.aligned.m8n8.x4.shared.b16 {%0,%1,%2,%3}, [%4];"  \
        : "=r"((r)[0]), "=r"((r)[1]), "=r"((r)[2]), "=r"((r)[3]) : "r"(addr))

// ---------------- FP16 tensor-core GEMM (R8-best config) -------------------------
// C[M,N] = A[M,K](fp16 rm) @ Bt[N,K](fp16 rm)^T + bias[N]
// mode 0: fp32 store (+bias). mode 1: fused chunk-scan epilogue (fp16 pair store)
//         + last-block-per-(batch,colblk) carry scan.
// mode 2: fp16 store, no bias.
#define BM 128
#define BN 128
#define BK 64
#define ASTR 72
#define AS_HALFS (BM*ASTR)
#define BS_HALFS (BN*ASTR)
#define STG_HALFS (AS_HALFS+BS_HALFS)
#define STAGES 3
#define SMEM_BYTES (STAGES*STG_HALFS*2)   // 110592
#define SSTR 68

__global__ void __launch_bounds__(256, 2) gemm_f16(
    const __half* __restrict__ A, const __half* __restrict__ Bt,
    const float* __restrict__ bias, const float* __restrict__ bias2,
    float* __restrict__ C,
    int K, int N, int mode, const float* __restrict__ log_a)
{
    extern __shared__ __half smh[];

    const int tid  = threadIdx.x;
    const int lane = tid & 31;
    const int warp = tid >> 5;
    const int g    = lane >> 2;
    const int tig  = lane & 3;
    const int wm   = warp & 1;
    const int wn   = warp >> 1;
    const int row0 = blockIdx.y * BM;
    const int col0 = blockIdx.x * BN;

    float acc[4][4][4];
    #pragma unroll
    for (int i = 0; i < 4; i++)
        #pragma unroll
        for (int j = 0; j < 4; j++)
            #pragma unroll
            for (int r = 0; r < 4; r++) acc[i][j][r] = 0.f;

    const int NT = K / BK;

    const uint32_t S0 = (uint32_t)__cvta_generic_to_shared(smh);
    const uint32_t aoff = ((wm * 64 + (lane & 15)) * ASTR + (lane >> 4) * 8) * 2;
    const uint32_t boff = (AS_HALFS + (wn * 32 + (lane & 7) + (lane >> 4) * 8) * ASTR
                           + ((lane >> 3) & 1) * 8) * 2;

    auto load_tiles = [&](int st, int kt) {
        __half* As = smh + st * STG_HALFS;
        __half* Bs = As + AS_HALFS;
        const __half* gA = A  + (size_t)row0 * K + kt * BK;
        const __half* gB = Bt + (size_t)col0 * K + kt * BK;
        #pragma unroll
        for (int i = 0; i < 4; i++) {
            int idx = tid + 256 * i;
            int r = idx >> 3, c = idx & 7;
            cp16(As + r * ASTR + c * 8, gA + (size_t)r * K + c * 8);
        }
        #pragma unroll
        for (int i = 0; i < 4; i++) {
            int idx = tid + 256 * i;
            int r = idx >> 3, c = idx & 7;
            cp16(Bs + r * ASTR + c * 8, gB + (size_t)r * K + c * 8);
        }
    };

    load_tiles(0, 0);
    asm volatile("cp.async.commit_group;\n");
    load_tiles(1, 1);
    asm volatile("cp.async.commit_group;\n");
    asm volatile("cp.async.wait_group 1;\n");
    __syncthreads();

    for (int kt = 0; kt < NT; kt++) {
        if (kt + 2 < NT) load_tiles((kt + 2) % STAGES, kt + 2);
        asm volatile("cp.async.commit_group;\n");

        const int st = kt % STAGES;
        const uint32_t aBase = S0 + st * (STG_HALFS * 2) + aoff;
        const uint32_t bBase = S0 + st * (STG_HALFS * 2) + boff;
        #pragma unroll
        for (int ks = 0; ks < 4; ks++) {
            uint32_t af[4][4], bf[2][4];
            #pragma unroll
            for (int mt = 0; mt < 4; mt++)
                LDSM4(af[mt], aBase + (mt * 16 * ASTR + ks * 16) * 2);
            #pragma unroll
            for (int ntp = 0; ntp < 2; ntp++)
                LDSM4(bf[ntp], bBase + (ntp * 16 * ASTR + ks * 16) * 2);
            #pragma unroll
            for (int mt = 0; mt < 4; mt++)
                #pragma unroll
                for (int nt = 0; nt < 4; nt++)
                    mma_f16(acc[mt][nt], af[mt],
                            bf[nt >> 1][(nt & 1) * 2], bf[nt >> 1][(nt & 1) * 2 + 1]);
        }

        asm volatile("cp.async.wait_group 1;\n");
        __syncthreads();
    }

    if (mode == 0) {
        #pragma unroll
        for (int nt = 0; nt < 4; nt++) {
            int c = col0 + wn * 32 + nt * 8 + 2 * tig;
            float b0 = 0.f, b1 = 0.f;
            if (bias) { b0 = bias[c]; b1 = bias[c + 1]; }
            #pragma unroll
            for (int mt = 0; mt < 4; mt++) {
                int r = row0 + wm * 64 + mt * 16 + g;
                float2 v0 = make_float2(acc[mt][nt][0] + b0, acc[mt][nt][1] + b1);
                float2 v1 = make_float2(acc[mt][nt][2] + b0, acc[mt][nt][3] + b1);
                *(float2*)(C + (size_t)r * N + c)       = v0;
                *(float2*)(C + (size_t)(r + 8) * N + c) = v1;
            }
        }
        return;
    }

    if (mode == 2) {   // fp16 store, no bias
        __half2* Ch = (__half2*)C;
        #pragma unroll
        for (int nt = 0; nt < 4; nt++) {
            int c = col0 + wn * 32 + nt * 8 + 2 * tig;
            #pragma unroll
            for (int mt = 0; mt < 4; mt++) {
                int r = row0 + wm * 64 + mt * 16 + g;
                Ch[((size_t)r * N + c) >> 1]       = __floats2half2_rn(acc[mt][nt][0], acc[mt][nt][1]);
                Ch[((size_t)(r + 8) * N + c) >> 1] = __floats2half2_rn(acc[mt][nt][2], acc[mt][nt][3]);
            }
        }
        return;
    }

    // ---- mode 1: fused chunk-local scan epilogue (bias = b_ih, bias2 = b_gate) ----
    float* sA = (float*)smh;            // alpha [128][SSTR]
    float* sB = sA + 128 * SSTR;        // beta
    float* sD = sB + 128 * SSTR;        // segment prefix products [4][64]
    float* sC = sD + 4 * 64;            // segment prefix states   [4][64]

    #pragma unroll
    for (int nt = 0; nt < 4; nt++) {
        const int c    = wn * 32 + nt * 8 + 2 * tig;       // local, even
        const int hloc = c >> 1;
        const int hg   = (col0 >> 1) + hloc;
        const float bi = bias[hg];
        const float bg = bias2[hg];
        const float av = expf(log_a[hg]);
        #pragma unroll
        for (int mt = 0; mt < 4; mt++) {
            const int r = wm * 64 + mt * 16 + g;
            {
                float ih = acc[mt][nt][0] + bi;
                float gp = acc[mt][nt][1] + bg;
                float gt = 1.f / (1.f + __expf(-gp));
                sA[r * SSTR + hloc] = (1.f - gt) * av;
                sB[r * SSTR + hloc] = gt * ih;
            }
            {
                float ih = acc[mt][nt][2] + bi;
                float gp = acc[mt][nt][3] + bg;
                float gt = 1.f / (1.f + __expf(-gp));
                sA[(r + 8) * SSTR + hloc] = (1.f - gt) * av;
                sB[(r + 8) * SSTR + hloc] = gt * ih;
            }
        }
    }
    __syncthreads();

    // phase 1: 4 segments of 32 steps, all 256 threads busy
    {
        const int h = tid & 63, seg = tid >> 6;
        float P = 1.f, hl = 0.f;
        int base = (seg * 32) * SSTR + h;
        #pragma unroll 8
        for (int i = 0; i < 32; i++, base += SSTR) {
            float al = sA[base], be = sB[base];
            P *= al;
            hl = fmaf(al, hl, be);
            sA[base] = P;
            sB[base] = hl;
        }
    }
    __syncthreads();

    // phase 2: per-channel segment prefixes (exclusive)
    if (tid < 64) {
        const int h = tid;
        float A0 = sA[31 * SSTR + h], B0 = sB[31 * SSTR + h];
        float A1 = sA[63 * SSTR + h], B1 = sB[63 * SSTR + h];
        float A2 = sA[95 * SSTR + h], B2 = sB[95 * SSTR + h];
        sD[0 * 64 + h] = 1.f;  sC[0 * 64 + h] = 0.f;
        sD[1 * 64 + h] = A0;   sC[1 * 64 + h] = B0;
        float D2 = A0 * A1;
        float C2 = fmaf(A1, B0, B1);
        sD[2 * 64 + h] = D2;       sC[2 * 64 + h] = C2;
        sD[3 * 64 + h] = D2 * A2;  sC[3 * 64 + h] = fmaf(A2, C2, B2);
    }
    __syncthreads();

    // phase 3: fixup + store (P, h_local) as __half2; fp32 carries at t=127
    const int bb  = row0 / T_;
    const int chh = (row0 - bb * T_) >> 7;
    __half2* Ch = (__half2*)C;
    #pragma unroll
    for (int k = 0; k < 32; k++) {
        const int e = tid + 256 * k;
        const int t = e >> 6, h = e & 63;
        const int seg = t >> 5;
        const float Pw  = sA[t * SSTR + h];
        const float hlw = sB[t * SSTR + h];
        const float P  = Pw * sD[seg * 64 + h];
        const float hl = fmaf(sC[seg * 64 + h], Pw, hlw);
        const int hg = (col0 >> 1) + h;
        Ch[(size_t)(row0 + t) * (NPRE / 2) + hg] = __floats2half2_rn(P, hl);
        if (t == 127) {
            const int ci = (bb * NC + chh) * H_ + hg;
            g_cA[ci] = P;
            g_cB[ci] = hl;
        }
    }

    // ---- last-block-per-(batch, colblk) carry scan ----
    __shared__ int s_last;
    __threadfence();          // make this block's g_cA/g_cB visible device-wide
    __syncthreads();
    if (tid == 0) {
        int prev = atomicAdd(&g_cnt[bb * NCOLB + blockIdx.x], 1);
        s_last = (prev == NC - 1) ? 1 : 0;
    }
    __syncthreads();
    if (s_last) {
        __threadfence();      // ensure we observe all other blocks' carry writes
        if (tid < 64) {
            const int hg = (col0 >> 1) + tid;
            float c = 0.f;
            #pragma unroll 4
            for (int ch = 0; ch < NC; ch++) {
                const int i = (bb * NC + ch) * H_ + hg;
                g_cP[i] = c;
                c = fmaf(g_cA[i], c, g_cB[i]);
            }
        }
        if (tid == 0) g_cnt[bb * NCOLB + blockIdx.x] = 0;   // self-reset for graph replay
    }
}

// ---------------- pre-passes -----------------------------------------------------
__global__ void __launch_bounds__(256) conv_h8(const float4* __restrict__ in,
                                               uint4* __restrict__ out)
{
    const size_t i = (size_t)blockIdx.x * 256 + threadIdx.x;
    float4 v0 = in[2 * i], v1 = in[2 * i + 1];
    __half2 h0 = __floats2half2_rn(v0.x, v0.y);
    __half2 h1 = __floats2half2_rn(v0.z, v0.w);
    __half2 h2 = __floats2half2_rn(v1.x, v1.y);
    __half2 h3 = __floats2half2_rn(v1.z, v1.w);
    uint4 o;
    o.x = *(uint32_t*)&h0; o.y = *(uint32_t*)&h1;
    o.z = *(uint32_t*)&h2; o.w = *(uint32_t*)&h3;
    out[i] = o;
}

// out[C][R] = fp16(in[R][C]^T)
__global__ void __launch_bounds__(256) trans_h(const float* __restrict__ in,
                                               __half* __restrict__ out,
                                               int R, int C)
{
    __shared__ float t[32][33];
    int bx = blockIdx.x * 32, by = blockIdx.y * 32;
    #pragma unroll
    for (int j = 0; j < 32; j += 8)
        t[threadIdx.y + j][threadIdx.x] =
            in[(size_t)(by + threadIdx.y + j) * C + bx + threadIdx.x];
    __syncthreads();
    #pragma unroll
    for (int j = 0; j < 32; j += 8)
        out[(size_t)(bx + threadIdx.y + j) * R + by + threadIdx.x] =
            __float2half_rn(t[threadIdx.x][threadIdx.y + j]);
}

// interleaved transpose: out[2*col + sel][row] = fp16(in[row][col]); in [R][C]
__global__ void __launch_bounds__(256) trans_h_il(const float* __restrict__ in,
                                                  __half* __restrict__ out,
                                                  int R, int C, int sel)
{
    __shared__ float t[32][33];
    int bx = blockIdx.x * 32, by = blockIdx.y * 32;
    #pragma unroll
    for (int j = 0; j < 32; j += 8)
        t[threadIdx.y + j][threadIdx.x] =
            in[(size_t)(by + threadIdx.y + j) * C + bx + threadIdx.x];
    __syncthreads();
    #pragma unroll
    for (int j = 0; j < 32; j += 8)
        out[(size_t)(2 * (bx + threadIdx.y + j) + sel) * R + by + threadIdx.x] =
            __float2half_rn(t[threadIdx.x][threadIdx.y + j]);
}

__global__ void __launch_bounds__(256) bias_comb_part(const float* __restrict__ b_out,
                                                      const float* __restrict__ W_proj)
{
    const int d = blockIdx.x * 256 + threadIdx.x;
    const int p = blockIdx.y;
    float acc = 0.f;
    #pragma unroll 8
    for (int hh = p * 64; hh < p * 64 + 64; hh++)
        acc = fmaf(b_out[hh], W_proj[(size_t)hh * D_ + d], acc);
    g_bcp[p * D_ + d] = acc;
}
__global__ void __launch_bounds__(256) bias_comb_final(const float* __restrict__ b_proj)
{
    const int d = blockIdx.x * 256 + threadIdx.x;
    float acc = b_proj[d];
    #pragma unroll
    for (int p = 0; p < BCK; p++) acc += g_bcp[p * D_ + d];
    g_bc[d] = acc;
}

// ---------------- carry fix-up + LayerNorm (fp16 in/out) -------------------------
__global__ void __launch_bounds__(256) fix_ln(const float* __restrict__ ln_g,
                                              const float* __restrict__ ln_b)
{
    const int row = blockIdx.x;
    const int b = row / T_, t = row - b * T_;
    const int ch = t / CH;
    const int tx = threadIdx.x;
    const __half2* ph_row = (const __half2*)g_preh + (size_t)row * (NPRE / 2);

    float hv[4];
    float s = 0.f, s2 = 0.f;
    #pragma unroll
    for (int j = 0; j < 4; j++) {
        const int h = tx + j * 256;
        const float2 ph = __half22float2(ph_row[h]);
        const float c = g_cP[(b * NC + ch) * H_ + h];
        const float v = fmaf(c, ph.x, ph.y);
        hv[j] = v;
        s += v;
        s2 = fmaf(v, v, s2);
    }

    __shared__ float rs[8], rs2[8];
    #pragma unroll
    for (int o = 16; o > 0; o >>= 1) {
        s  += __shfl_xor_sync(0xffffffffu, s,  o);
        s2 += __shfl_xor_sync(0xffffffffu, s2, o);
    }
    const int w = tx >> 5, l = tx & 31;
    if (l == 0) { rs[w] = s; rs2[w] = s2; }
    __syncthreads();
    if (w == 0) {
        s  = (l < 8) ? rs[l]  : 0.f;
        s2 = (l < 8) ? rs2[l] : 0.f;
        #pragma unroll
        for (int o = 4; o > 0; o >>= 1) {
            s  += __shfl_xor_sync(0xffffffffu, s,  o);
            s2 += __shfl_xor_sync(0xffffffffu, s2, o);
        }
        if (l == 0) { rs[0] = s; rs2[0] = s2; }
    }
    __syncthreads();
    const float mu  = rs[0] * (1.f / H_);
    const float var = rs2[0] * (1.f / H_) - mu * mu;
    const float rstd = rsqrtf(var + 1e-5f);

    #pragma unroll
    for (int j = 0; j < 4; j++) {
        const int h = tx + j * 256;
        g_hn[(size_t)row * H_ + h] =
            __float2half_rn(fmaf((hv[j] - mu) * rstd, ln_g[h], ln_b[h]));
    }
}

// ------------------------------- launch -------------------------------------------
extern "C" void kernel_launch(void* const* d_in, const int* in_sizes, int n_in,
                              void* d_out, int out_size)
{
    const float* x      = (const float*)d_in[0];
    const float* W_ih   = (const float*)d_in[1];
    const float* b_ih   = (const float*)d_in[2];
    const float* W_gate = (const float*)d_in[3];
    const float* b_gate = (const float*)d_in[4];
    const float* log_a  = (const float*)d_in[5];
    const float* ln_g   = (const float*)d_in[6];
    const float* ln_b   = (const float*)d_in[7];
    const float* W_out  = (const float*)d_in[8];
    const float* b_out  = (const float*)d_in[9];
    const float* W_proj = (const float*)d_in[10];
    const float* b_proj = (const float*)d_in[11];
    float* out = (float*)d_out;

    cudaFuncSetAttribute(gemm_f16, cudaFuncAttributeMaxDynamicSharedMemorySize, SMEM_BYTES);

    __half *p_xh, *p_preh, *p_hn, *p_WcatT, *p_WoutH, *p_WprojT, *p_WcT;
    float *p_bc;
    cudaGetSymbolAddress((void**)&p_xh,     g_xh);
    cudaGetSymbolAddress((void**)&p_preh,   g_preh);
    cudaGetSymbolAddress((void**)&p_hn,     g_hn);
    cudaGetSymbolAddress((void**)&p_WcatT,  g_WcatT);
    cudaGetSymbolAddress((void**)&p_WoutH,  g_WoutH);
    cudaGetSymbolAddress((void**)&p_WprojT, g_WprojT);
    cudaGetSymbolAddress((void**)&p_WcT,    g_WcT);
    cudaGetSymbolAddress((void**)&p_bc,     g_bc);

    // lazily created side stream + events (host resources only)
    static cudaStream_t s2 = nullptr;
    static cudaEvent_t ev_fork = nullptr, ev_xw = nullptr, ev_wc = nullptr;
    if (!s2) {
        cudaStreamCreateWithFlags(&s2, cudaStreamNonBlocking);
        cudaEventCreateWithFlags(&ev_fork, cudaEventDisableTiming);
        cudaEventCreateWithFlags(&ev_xw,   cudaEventDisableTiming);
        cudaEventCreateWithFlags(&ev_wc,   cudaEventDisableTiming);
    }

    const dim3 blk(256);
    const dim3 tblk(32, 8);
    const dim3 tg(32, 32);
    const int  CONV_HALF_BLKS = (int)((size_t)M_ * D_ / 8 / 256 / 2);  // 8192
    const size_t XHALF4  = (size_t)M_ * D_ / 8;   // float4 count of half the x tensor
    const size_t XHALF16 = (size_t)M_ * D_ / 16;  // uint4  count of half the fp16 x

    // fork side stream at graph entry
    cudaEventRecord(ev_fork, 0);
    cudaStreamWaitEvent(s2, ev_fork, 0);

    // ---- balanced GEMM1 prologue across both streams ----
    // main: W_ih transpose + x conversion (first half)
    trans_h_il<<<tg, tblk>>>(W_ih, p_WcatT, D_, H_, 0);
    conv_h8<<<CONV_HALF_BLKS, blk>>>((const float4*)x, (uint4*)p_xh);
    // s2:   W_gate transpose + x conversion (second half)
    trans_h_il<<<tg, tblk, 0, s2>>>(W_gate, p_WcatT, D_, H_, 1);
    conv_h8<<<CONV_HALF_BLKS, blk, 0, s2>>>((const float4*)x + XHALF4,
                                            (uint4*)p_xh + XHALF16);
    cudaEventRecord(ev_xw, s2);

    // ---- s2 continues with the WcT weight chain (needed only by final GEMM) ----
    trans_h<<<tg, tblk, 0, s2>>>(W_proj, p_WprojT, H_, D_);
    conv_h8<<<(int)((size_t)H_*H_/8/256), blk, 0, s2>>>((const float4*)W_out, (uint4*)p_WoutH);
    bias_comb_part<<<dim3(D_/256, BCK), blk, 0, s2>>>(b_out, W_proj);
    bias_comb_final<<<D_/256, blk, 0, s2>>>(b_proj);
    gemm_f16<<<dim3(H_/BN, D_/BM), blk, SMEM_BYTES, s2>>>(p_WprojT, p_WoutH, nullptr, nullptr,
                                                          (float*)p_WcT, H_, H_, 2, nullptr);
    cudaEventRecord(ev_wc, s2);

    // ---- main: fused GEMM1 (ih|gate + chunk scan + in-kernel carry scan) ----
    cudaStreamWaitEvent(0, ev_xw, 0);
    gemm_f16<<<dim3(NPRE/BN, M_/BM), blk, SMEM_BYTES>>>(p_xh, p_WcatT, b_ih, b_gate,
                                                        (float*)p_preh, D_, NPRE, 1, log_a);

    // carry fix-up + layernorm (g_cP fully written inside GEMM1)
    fix_ln<<<M_, blk>>>(ln_g, ln_b);

    // join side stream, then final GEMM: out = hn @ Wc + bc
    cudaStreamWaitEvent(0, ev_wc, 0);
    gemm_f16<<<dim3(D_/BN, M_/BM), blk, SMEM_BYTES>>>(p_hn, p_WcT, p_bc, nullptr, out,
                                                      H_, D_, 0, nullptr);
}